// round 1
// baseline (speedup 1.0000x reference)
#include <cuda_runtime.h>

// SceneContraction: means = contract(mean); cov_out = J cov J^T where
// J = jac(contract_gauss)(mean) = g*I + c*x x^T (symmetric),
//   g = (2 - 1/m)/m,  c = 2(1-m)/m^4,  m = ||x||.
// Mask m < 1: passthrough for both mean and cov.
// Purely HBM-bound: 96 B/sample * 4.19M samples = 402 MB traffic.

__global__ __launch_bounds__(256) void scene_contraction_kernel(
    const float* __restrict__ mean,   // [N,3]
    const float* __restrict__ cov,    // [N,3,3]
    float* __restrict__ out_mean,     // [N,3]
    float* __restrict__ out_cov,      // [N,3,3]
    int n)
{
    int i = blockIdx.x * blockDim.x + threadIdx.x;
    if (i >= n) return;

    const float* xp = mean + 3ull * i;
    float x0 = xp[0], x1 = xp[1], x2 = xp[2];

    const float* cp = cov + 9ull * i;
    float c00 = cp[0], c01 = cp[1], c02 = cp[2];
    float c10 = cp[3], c11 = cp[4], c12 = cp[5];
    float c20 = cp[6], c21 = cp[7], c22 = cp[8];

    float m2 = fmaf(x0, x0, fmaf(x1, x1, x2 * x2));
    float m  = sqrtf(m2);

    float* om = out_mean + 3ull * i;
    float* oc = out_cov  + 9ull * i;

    if (m < 1.0f) {
        om[0] = x0; om[1] = x1; om[2] = x2;
        oc[0] = c00; oc[1] = c01; oc[2] = c02;
        oc[3] = c10; oc[4] = c11; oc[5] = c12;
        oc[6] = c20; oc[7] = c21; oc[8] = c22;
    } else {
        float inv  = 1.0f / m;            // 1/m
        float g    = (2.0f - inv) * inv;  // (2 - 1/m)/m
        float inv2 = inv * inv;
        float cc   = 2.0f * (1.0f - m) * inv2 * inv2;  // 2(1-m)/m^4

        // contracted mean = g * x
        om[0] = g * x0; om[1] = g * x1; om[2] = g * x2;

        // J = g*I + cc * x x^T (symmetric)
        float J00 = fmaf(cc, x0 * x0, g);
        float J11 = fmaf(cc, x1 * x1, g);
        float J22 = fmaf(cc, x2 * x2, g);
        float J01 = cc * x0 * x1;
        float J02 = cc * x0 * x2;
        float J12 = cc * x1 * x2;

        // B = J * C
        float b00 = J00*c00 + J01*c10 + J02*c20;
        float b01 = J00*c01 + J01*c11 + J02*c21;
        float b02 = J00*c02 + J01*c12 + J02*c22;
        float b10 = J01*c00 + J11*c10 + J12*c20;
        float b11 = J01*c01 + J11*c11 + J12*c21;
        float b12 = J01*c02 + J11*c12 + J12*c22;
        float b20 = J02*c00 + J12*c10 + J22*c20;
        float b21 = J02*c01 + J12*c11 + J22*c21;
        float b22 = J02*c02 + J12*c12 + J22*c22;

        // O = B * J^T = B * J (J symmetric)
        oc[0] = b00*J00 + b01*J01 + b02*J02;
        oc[1] = b00*J01 + b01*J11 + b02*J12;
        oc[2] = b00*J02 + b01*J12 + b02*J22;
        oc[3] = b10*J00 + b11*J01 + b12*J02;
        oc[4] = b10*J01 + b11*J11 + b12*J12;
        oc[5] = b10*J02 + b11*J12 + b12*J22;
        oc[6] = b20*J00 + b21*J01 + b22*J02;
        oc[7] = b20*J01 + b21*J11 + b22*J12;
        oc[8] = b20*J02 + b21*J12 + b22*J22;
    }
}

extern "C" void kernel_launch(void* const* d_in, const int* in_sizes, int n_in,
                              void* d_out, int out_size)
{
    const float* mean = (const float*)d_in[0];   // [N,3]
    const float* cov  = (const float*)d_in[1];   // [N,3,3]
    int n = in_sizes[0] / 3;

    float* out_mean = (float*)d_out;             // first N*3 elements
    float* out_cov  = (float*)d_out + 3ull * n;  // next N*9 elements

    int threads = 256;
    int blocks  = (n + threads - 1) / threads;
    scene_contraction_kernel<<<blocks, threads>>>(mean, cov, out_mean, out_cov, n);
}

// round 2
// speedup vs baseline: 1.9919x; 1.9919x over previous
#include <cuda_runtime.h>

// SceneContraction, smem-staged for fully coalesced 128-bit global access.
// means = contract(mean); cov_out = J cov J (J symmetric) for ||x||>=1, else passthrough.
// J = g*I + c*x x^T,  g=(2-1/m)/m,  c=2(1-m)/m^4,  m=||x||.

#define TPB 256
#define M4 (TPB * 3 / 4)   // 192 float4 of mean per block
#define C4 (TPB * 9 / 4)   // 576 float4 of cov per block

__global__ __launch_bounds__(TPB) void scene_contraction_kernel(
    const float* __restrict__ mean,   // [N,3]
    const float* __restrict__ cov,    // [N,3,3]
    float* __restrict__ out_mean,     // [N,3]
    float* __restrict__ out_cov,      // [N,3,3]
    int n)
{
    __shared__ float4 s_mean4[M4];
    __shared__ float4 s_cov4[C4];
    float* s_mean = reinterpret_cast<float*>(s_mean4);
    float* s_cov  = reinterpret_cast<float*>(s_cov4);

    const int t = threadIdx.x;
    const int base = blockIdx.x * TPB;   // first sample of this block

    if (base + TPB <= n) {
        // ---- coalesced load into smem ----
        const float4* gm = reinterpret_cast<const float4*>(mean) + (size_t)blockIdx.x * M4;
        const float4* gc = reinterpret_cast<const float4*>(cov)  + (size_t)blockIdx.x * C4;
        if (t < M4) s_mean4[t] = gm[t];
        #pragma unroll
        for (int i = t; i < C4; i += TPB) s_cov4[i] = gc[i];
        __syncthreads();

        // ---- per-sample compute from smem (stride 3 / 9: bank-conflict-free) ----
        float x0 = s_mean[3*t+0], x1 = s_mean[3*t+1], x2 = s_mean[3*t+2];
        float c00 = s_cov[9*t+0], c01 = s_cov[9*t+1], c02 = s_cov[9*t+2];
        float c10 = s_cov[9*t+3], c11 = s_cov[9*t+4], c12 = s_cov[9*t+5];
        float c20 = s_cov[9*t+6], c21 = s_cov[9*t+7], c22 = s_cov[9*t+8];

        float m2 = fmaf(x0, x0, fmaf(x1, x1, x2 * x2));
        float m  = sqrtf(m2);

        float r0 = x0, r1 = x1, r2 = x2;
        float o00 = c00, o01 = c01, o02 = c02;
        float o10 = c10, o11 = c11, o12 = c12;
        float o20 = c20, o21 = c21, o22 = c22;

        if (m >= 1.0f) {
            float inv  = 1.0f / m;
            float g    = (2.0f - inv) * inv;
            float inv2 = inv * inv;
            float cc   = 2.0f * (1.0f - m) * inv2 * inv2;

            r0 = g * x0; r1 = g * x1; r2 = g * x2;

            float J00 = fmaf(cc, x0 * x0, g);
            float J11 = fmaf(cc, x1 * x1, g);
            float J22 = fmaf(cc, x2 * x2, g);
            float J01 = cc * x0 * x1;
            float J02 = cc * x0 * x2;
            float J12 = cc * x1 * x2;

            float b00 = J00*c00 + J01*c10 + J02*c20;
            float b01 = J00*c01 + J01*c11 + J02*c21;
            float b02 = J00*c02 + J01*c12 + J02*c22;
            float b10 = J01*c00 + J11*c10 + J12*c20;
            float b11 = J01*c01 + J11*c11 + J12*c21;
            float b12 = J01*c02 + J11*c12 + J12*c22;
            float b20 = J02*c00 + J12*c10 + J22*c20;
            float b21 = J02*c01 + J12*c11 + J22*c21;
            float b22 = J02*c02 + J12*c12 + J22*c22;

            o00 = b00*J00 + b01*J01 + b02*J02;
            o01 = b00*J01 + b01*J11 + b02*J12;
            o02 = b00*J02 + b01*J12 + b02*J22;
            o10 = b10*J00 + b11*J01 + b12*J02;
            o11 = b10*J01 + b11*J11 + b12*J12;
            o12 = b10*J02 + b11*J12 + b12*J22;
            o20 = b20*J00 + b21*J01 + b22*J02;
            o21 = b20*J01 + b21*J11 + b22*J12;
            o22 = b20*J02 + b21*J12 + b22*J22;
        }

        __syncthreads();   // everyone done reading smem

        s_mean[3*t+0] = r0; s_mean[3*t+1] = r1; s_mean[3*t+2] = r2;
        s_cov[9*t+0] = o00; s_cov[9*t+1] = o01; s_cov[9*t+2] = o02;
        s_cov[9*t+3] = o10; s_cov[9*t+4] = o11; s_cov[9*t+5] = o12;
        s_cov[9*t+6] = o20; s_cov[9*t+7] = o21; s_cov[9*t+8] = o22;
        __syncthreads();

        // ---- coalesced store from smem ----
        float4* om = reinterpret_cast<float4*>(out_mean) + (size_t)blockIdx.x * M4;
        float4* oc = reinterpret_cast<float4*>(out_cov)  + (size_t)blockIdx.x * C4;
        if (t < M4) om[t] = s_mean4[t];
        #pragma unroll
        for (int i = t; i < C4; i += TPB) oc[i] = s_cov4[i];
    } else {
        // ---- scalar tail path ----
        int i = base + t;
        if (i >= n) return;
        const float* xp = mean + 3ull * i;
        float x0 = xp[0], x1 = xp[1], x2 = xp[2];
        const float* cp = cov + 9ull * i;
        float c00 = cp[0], c01 = cp[1], c02 = cp[2];
        float c10 = cp[3], c11 = cp[4], c12 = cp[5];
        float c20 = cp[6], c21 = cp[7], c22 = cp[8];

        float m2 = fmaf(x0, x0, fmaf(x1, x1, x2 * x2));
        float m  = sqrtf(m2);
        float* om = out_mean + 3ull * i;
        float* oc = out_cov  + 9ull * i;
        if (m < 1.0f) {
            om[0]=x0; om[1]=x1; om[2]=x2;
            oc[0]=c00; oc[1]=c01; oc[2]=c02;
            oc[3]=c10; oc[4]=c11; oc[5]=c12;
            oc[6]=c20; oc[7]=c21; oc[8]=c22;
        } else {
            float inv  = 1.0f / m;
            float g    = (2.0f - inv) * inv;
            float inv2 = inv * inv;
            float cc   = 2.0f * (1.0f - m) * inv2 * inv2;
            om[0] = g*x0; om[1] = g*x1; om[2] = g*x2;
            float J00 = fmaf(cc, x0*x0, g);
            float J11 = fmaf(cc, x1*x1, g);
            float J22 = fmaf(cc, x2*x2, g);
            float J01 = cc*x0*x1, J02 = cc*x0*x2, J12 = cc*x1*x2;
            float b00 = J00*c00 + J01*c10 + J02*c20;
            float b01 = J00*c01 + J01*c11 + J02*c21;
            float b02 = J00*c02 + J01*c12 + J02*c22;
            float b10 = J01*c00 + J11*c10 + J12*c20;
            float b11 = J01*c01 + J11*c11 + J12*c21;
            float b12 = J01*c02 + J11*c12 + J12*c22;
            float b20 = J02*c00 + J12*c10 + J22*c20;
            float b21 = J02*c01 + J12*c11 + J22*c21;
            float b22 = J02*c02 + J12*c12 + J22*c22;
            oc[0] = b00*J00 + b01*J01 + b02*J02;
            oc[1] = b00*J01 + b01*J11 + b02*J12;
            oc[2] = b00*J02 + b01*J12 + b02*J22;
            oc[3] = b10*J00 + b11*J01 + b12*J02;
            oc[4] = b10*J01 + b11*J11 + b12*J12;
            oc[5] = b10*J02 + b11*J12 + b12*J22;
            oc[6] = b20*J00 + b21*J01 + b22*J02;
            oc[7] = b20*J01 + b21*J11 + b22*J12;
            oc[8] = b20*J02 + b21*J12 + b22*J22;
        }
    }
}

extern "C" void kernel_launch(void* const* d_in, const int* in_sizes, int n_in,
                              void* d_out, int out_size)
{
    const float* mean = (const float*)d_in[0];   // [N,3]
    const float* cov  = (const float*)d_in[1];   // [N,3,3]
    int n = in_sizes[0] / 3;

    float* out_mean = (float*)d_out;
    float* out_cov  = (float*)d_out + 3ull * n;

    int blocks = (n + TPB - 1) / TPB;
    scene_contraction_kernel<<<blocks, TPB>>>(mean, cov, out_mean, out_cov, n);
}